// round 1
// baseline (speedup 1.0000x reference)
#include <cuda_runtime.h>
#include <cstdint>

// VectorQuantizer: z_e [32, 64, 32, 32] f32, emb [1024, 64] f32
// Outputs: quantized [32,64,32,32] f32 (2097152) then indices [32,1024] as f32 (32768)
//
// Reference numerics replicated exactly:
//   A      = sum_c z^2              (per-row constant; order-insensitive up to an
//                                    exact ulp shift -> argmin invariant)
//   es[k]  = sum_c e^2
//   t1     = fl(A + es[k])          (separate FADD, NOT fused)
//   d      = fl(t1 - 2*dot)         (fmaf(-2,dot,t1); 2*dot is exact so identical
//                                    rounding to the reference's t1 - fl(2*dot))
//   argmin with first-index tie-break: ascending k, strict '<'.

#define N_ROWS   32768      // 32 batches * 1024 positions
#define KCODES   1024
#define CDIM     64
#define TK       64         // codebook tile rows per SMEM stage
#define CTA      256

__global__ __launch_bounds__(CTA, 1)
void vq_argmin_kernel(const float* __restrict__ z,
                      const float* __restrict__ emb,
                      float* __restrict__ out,
                      int out_size)
{
    __shared__ float4 e_sh[TK][CDIM / 4];   // 64 x 16 float4 = 16 KB
    __shared__ float  es_sh[TK];

    const int tid = threadIdx.x;
    const int row = blockIdx.x * CTA + tid;     // row in [0, 32768)
    const int b   = row >> 10;                  // batch
    const int n   = row & 1023;                 // h*32+w position

    // z_flat[b][n][c] = z[((b*64 + c)*1024) + n]
    const float* zp = z + (size_t)b * (CDIM * 1024) + n;

    // ---- load this thread's z row into registers (coalesced per c across warp) ----
    float4 z4[CDIM / 4];
#pragma unroll
    for (int c4 = 0; c4 < CDIM / 4; ++c4) {
        z4[c4].x = zp[(c4 * 4 + 0) * 1024];
        z4[c4].y = zp[(c4 * 4 + 1) * 1024];
        z4[c4].z = zp[(c4 * 4 + 2) * 1024];
        z4[c4].w = zp[(c4 * 4 + 3) * 1024];
    }

    // ---- A = sum_c z^2 (fp32 sequential) ----
    float A = 0.0f;
#pragma unroll
    for (int c4 = 0; c4 < CDIM / 4; ++c4) {
        A = fmaf(z4[c4].x, z4[c4].x, A);
        A = fmaf(z4[c4].y, z4[c4].y, A);
        A = fmaf(z4[c4].z, z4[c4].z, A);
        A = fmaf(z4[c4].w, z4[c4].w, A);
    }

    float dmin = __int_as_float(0x7f800000);    // +inf
    int   kmin = 0;

    const float4* embv = (const float4*)emb;    // 1024*16 float4 total; tile = 1024 float4

    // prefetch tile 0 into registers
    float4 pre[4];
#pragma unroll
    for (int i = 0; i < 4; ++i)
        pre[i] = embv[tid + i * CTA];

    for (int t = 0; t < KCODES / TK; ++t) {
        __syncthreads();    // previous tile fully consumed
        // stage prefetched tile into SMEM
#pragma unroll
        for (int i = 0; i < 4; ++i)
            ((float4*)e_sh)[tid + i * CTA] = pre[i];
        __syncthreads();

        // es[k] = sum_c e^2 for this tile
        if (tid < TK) {
            float s = 0.0f;
#pragma unroll
            for (int c4 = 0; c4 < CDIM / 4; ++c4) {
                float4 e = e_sh[tid][c4];
                s = fmaf(e.x, e.x, s);
                s = fmaf(e.y, e.y, s);
                s = fmaf(e.z, e.z, s);
                s = fmaf(e.w, e.w, s);
            }
            es_sh[tid] = s;
        }

        // prefetch next tile (LDGs overlap the compute below)
        if (t + 1 < KCODES / TK) {
#pragma unroll
            for (int i = 0; i < 4; ++i)
                pre[i] = embv[(t + 1) * (TK * CDIM / 4) + tid + i * CTA];
        }
        __syncthreads();    // es_sh ready

        // ---- score 64 codes, 4 at a time (4 independent FMA chains for ILP) ----
#pragma unroll 1
        for (int kk = 0; kk < TK; kk += 4) {
            float d0 = 0.0f, d1 = 0.0f, d2 = 0.0f, d3 = 0.0f;
#pragma unroll
            for (int c4 = 0; c4 < CDIM / 4; ++c4) {
                float4 zz = z4[c4];
                float4 a0 = e_sh[kk + 0][c4];
                float4 a1 = e_sh[kk + 1][c4];
                float4 a2 = e_sh[kk + 2][c4];
                float4 a3 = e_sh[kk + 3][c4];
                d0 = fmaf(zz.x, a0.x, d0); d0 = fmaf(zz.y, a0.y, d0);
                d0 = fmaf(zz.z, a0.z, d0); d0 = fmaf(zz.w, a0.w, d0);
                d1 = fmaf(zz.x, a1.x, d1); d1 = fmaf(zz.y, a1.y, d1);
                d1 = fmaf(zz.z, a1.z, d1); d1 = fmaf(zz.w, a1.w, d1);
                d2 = fmaf(zz.x, a2.x, d2); d2 = fmaf(zz.y, a2.y, d2);
                d2 = fmaf(zz.z, a2.z, d2); d2 = fmaf(zz.w, a2.w, d2);
                d3 = fmaf(zz.x, a3.x, d3); d3 = fmaf(zz.y, a3.y, d3);
                d3 = fmaf(zz.z, a3.z, d3); d3 = fmaf(zz.w, a3.w, d3);
            }
            const int kbase = t * TK + kk;
            // exact reference rounding sequence: t1 = fl(A + es); d = fl(t1 - 2*dot)
            float t0 = A + es_sh[kk + 0];
            float t1 = A + es_sh[kk + 1];
            float t2 = A + es_sh[kk + 2];
            float t3 = A + es_sh[kk + 3];
            float v0 = fmaf(-2.0f, d0, t0);
            float v1 = fmaf(-2.0f, d1, t1);
            float v2 = fmaf(-2.0f, d2, t2);
            float v3 = fmaf(-2.0f, d3, t3);
            if (v0 < dmin) { dmin = v0; kmin = kbase + 0; }
            if (v1 < dmin) { dmin = v1; kmin = kbase + 1; }
            if (v2 < dmin) { dmin = v2; kmin = kbase + 2; }
            if (v3 < dmin) { dmin = v3; kmin = kbase + 3; }
        }
    }

    // ---- epilogue: gather winning codebook row, scatter to [B,C,H,W] layout ----
    const float4* erow = (const float4*)(emb + (size_t)kmin * CDIM);
    float* outp = out + (size_t)b * (CDIM * 1024) + n;
#pragma unroll
    for (int c4 = 0; c4 < CDIM / 4; ++c4) {
        float4 e = erow[c4];
        outp[(c4 * 4 + 0) * 1024] = e.x;
        outp[(c4 * 4 + 1) * 1024] = e.y;
        outp[(c4 * 4 + 2) * 1024] = e.z;
        outp[(c4 * 4 + 3) * 1024] = e.w;
    }

    // indices output (as float), appended after quantized tensor if present
    const int idx_base = N_ROWS * CDIM;     // 2097152
    if (idx_base + row < out_size)
        out[idx_base + row] = (float)kmin;
}

extern "C" void kernel_launch(void* const* d_in, const int* in_sizes, int n_in,
                              void* d_out, int out_size)
{
    const float* z_e = (const float*)d_in[0];      // 2097152 elems
    const float* emb = (const float*)d_in[1];      // 65536 elems
    float* out = (float*)d_out;

    vq_argmin_kernel<<<N_ROWS / CTA, CTA>>>(z_e, emb, out, out_size);
}